// round 9
// baseline (speedup 1.0000x reference)
#include <cuda_runtime.h>
#include <cuda_bf16.h>
#include <math.h>
#include <stdint.h>

#define D     64
#define TM    64        // x rows per CTA
#define TK    64        // prototypes per CTA
#define KP    128       // total prototypes
#define NTH   256
#define ROWB  384       // bytes per B row; chunk0=hi @0, chunk2=lo @256

// smem layout
#define SM_B   0                      // 64 x 384B = 24576
#define SM_XF  24576                  // x fragment staging: 2048 x 8B = 16384
#define SM_P2  40960                  // 64 floats
#define SM_PS  (SM_P2 + 256)          // 64 floats
#define SM_DYN (SM_PS + 256)          // 41472 B

static __device__ __forceinline__ uint32_t sw(uint32_t off) {
    return off ^ ((off >> 3) & 0x70);
}

static __device__ __forceinline__ uint32_t smem_u32(const void* p) {
    uint32_t a;
    asm("{ .reg .u64 t; cvta.to.shared.u64 t, %1; cvt.u32.u64 %0, t; }" : "=r"(a) : "l"(p));
    return a;
}

static __device__ __forceinline__ void ldsm_x4(uint32_t* r, uint32_t addr) {
    asm volatile("ldmatrix.sync.aligned.m8n8.x4.shared.b16 {%0,%1,%2,%3}, [%4];"
                 : "=r"(r[0]), "=r"(r[1]), "=r"(r[2]), "=r"(r[3]) : "r"(addr));
}

static __device__ __forceinline__ void mma_bf16(float* c, const uint32_t* a,
                                                uint32_t b0, uint32_t b1) {
    asm volatile(
        "mma.sync.aligned.m16n8k16.row.col.f32.bf16.bf16.f32 "
        "{%0,%1,%2,%3}, {%4,%5,%6,%7}, {%8,%9}, {%0,%1,%2,%3};"
        : "+f"(c[0]), "+f"(c[1]), "+f"(c[2]), "+f"(c[3])
        : "r"(a[0]), "r"(a[1]), "r"(a[2]), "r"(a[3]), "r"(b0), "r"(b1));
}

static __device__ __forceinline__ void split2(float v0, float v1,
                                              uint32_t& hi, uint32_t& lo) {
    __nv_bfloat162 h = __floats2bfloat162_rn(v0, v1);
    float r0 = v0 - __bfloat162float(__low2bfloat16(h));
    float r1 = v1 - __bfloat162float(__high2bfloat16(h));
    __nv_bfloat162 l = __floats2bfloat162_rn(r0, r1);
    hi = *reinterpret_cast<uint32_t*>(&h);
    lo = *reinterpret_cast<uint32_t*>(&l);
}

// num2 = A^2 x2 - 2AB xy + B^2 p2  ==  den^2 - den*(1-x2)(1-p2)   (verified)
static __device__ __forceinline__ float epi(float xy, float x2, float Ba, float p2) {
    const float t   = fmaf(x2, p2, 1.0f);
    const float den = fmaxf(fmaf(-2.0f, xy, t), 1e-15f);
    const float bb  = fmaf(-Ba, p2, Ba);              // Ba*(1-p2)
    float G = fmaf(den, den, -(den * bb));            // = |num|^2
    G = fmaxf(G, 1e-30f);
    float s = G * rsqrtf(G);                          // sqrt(G)
    s = fminf(s, 0.99999f * den);                     // z <= 1 - 1e-5
    const float dist = (__log2f(den + s) - __log2f(den - s)) * 0.6931471805599453f;
    return -dist * dist;
}

// ---------------------------------------------------------------------------
// grid (N/64, 2), 256 threads, 4 CTAs/SM, single wave.
//  x A-fragments: cp.async -> smem staging (pre-shuffled), overlapped with
//  prototype projection + B split-bf16 conversion. MMA per R4-verified mapping.
// ---------------------------------------------------------------------------
__global__ void __launch_bounds__(NTH, 4)
geo_kernel(const float* __restrict__ x, const float* __restrict__ proto,
           float* __restrict__ out) {
    extern __shared__ char sm[];
    const uint32_t smb = smem_u32(sm);
    float* p2_s = (float*)(sm + SM_P2);
    float* ps_s = (float*)(sm + SM_PS);

    const int tid  = threadIdx.x;
    const int wid  = tid >> 5;
    const int lane = tid & 31;
    const int n0   = blockIdx.x * TM;
    const int k0   = blockIdx.y * TK;

    // ---- issue x-fragment cp.async first (overlaps all B work) ----
    // slot (t,v,wm,lane): row = wm*16 + (lane>>2) + (v&1)*8,
    //                     kf  = 2*(lane&3) + 16t + 8*(v>>1)
    #pragma unroll
    for (int e = 0; e < 8; ++e) {
        const int flat = e * NTH + tid;
        const int l   = flat & 31;
        const int wmm = (flat >> 5) & 3;
        const int tv  = flat >> 7;          // 0..15
        const int t   = tv >> 2, v = tv & 3;
        const int row = wmm * 16 + (l >> 2) + (v & 1) * 8;
        const int kf  = 2 * (l & 3) + t * 16 + (v >> 1) * 8;
        const float* src = x + (size_t)(n0 + row) * D + kf;
        const uint32_t dst = smb + SM_XF + (uint32_t)flat * 8;
        asm volatile("cp.async.ca.shared.global [%0], [%1], 8;" :: "r"(dst), "l"(src));
    }
    asm volatile("cp.async.commit_group;" ::: "memory");

    // ---- prototype projection scale + p^2 (tid < 64) ----
    if (tid < TK) {
        const float4* p4 = (const float4*)(proto) + (size_t)(k0 + tid) * (D / 4);
        float s = 0.f;
        #pragma unroll
        for (int i = 0; i < D / 4; ++i) {
            float4 v = p4[i];
            s += v.x * v.x + v.y * v.y + v.z * v.z + v.w * v.w;
        }
        const float n  = fmaxf(sqrtf(s), 1e-15f);
        const float sc = fminf(1.0f, 0.999f / n);   // (1-BALL_EPS)/sqrt(c)
        ps_s[tid] = sc;
        p2_s[tid] = s * sc * sc;
    }
    __syncthreads();

    // ---- B: split-bf16 into swizzled smem (hi @0, lo @+256B) ----
    {
        const float2* ps = (const float2*)(proto) + (size_t)k0 * (D / 2);
        #pragma unroll
        for (int it = 0; it < (TK * D / 2) / NTH; ++it) {   // 8 iters; warp = 1 row
            int row = it * 8 + wid;
            float sc = ps_s[row];
            float2 v = ps[row * 32 + lane];
            uint32_t hi, lo;
            split2(v.x * sc, v.y * sc, hi, lo);
            uint32_t base = (uint32_t)row * ROWB + (uint32_t)lane * 4;
            *(uint32_t*)(sm + SM_B + sw(base))       = hi;  // chunk0: hi
            *(uint32_t*)(sm + SM_B + sw(base + 256)) = lo;  // chunk2: lo
        }
    }
    asm volatile("cp.async.wait_group 0;" ::: "memory");
    __syncthreads();

    // ---- A fragments from smem staging: split + exact x^2 ----
    const int wm = wid & 3;
    const int wn = wid >> 2;
    const int r0 = wm * 16 + (lane >> 2);

    uint32_t ahi[16], alo[16];
    float s0 = 0.f, s1 = 0.f;
    #pragma unroll
    for (int t = 0; t < 4; ++t) {
        const char* base = sm + SM_XF + ((t * 4) * 4 + wm) * 256 + lane * 8;
        float2 v00 = *(const float2*)(base);            // v=0: (r0,   k)
        float2 v10 = *(const float2*)(base + 1024);     // v=1: (r0+8, k)
        float2 v01 = *(const float2*)(base + 2048);     // v=2: (r0,   k+8)
        float2 v11 = *(const float2*)(base + 3072);     // v=3: (r0+8, k+8)
        s0 += v00.x * v00.x + v00.y * v00.y + v01.x * v01.x + v01.y * v01.y;
        s1 += v10.x * v10.x + v10.y * v10.y + v11.x * v11.x + v11.y * v11.y;
        split2(v00.x, v00.y, ahi[4 * t + 0], alo[4 * t + 0]);
        split2(v10.x, v10.y, ahi[4 * t + 1], alo[4 * t + 1]);
        split2(v01.x, v01.y, ahi[4 * t + 2], alo[4 * t + 2]);
        split2(v11.x, v11.y, ahi[4 * t + 3], alo[4 * t + 3]);
    }
    s0 += __shfl_xor_sync(0xFFFFFFFFu, s0, 1);
    s0 += __shfl_xor_sync(0xFFFFFFFFu, s0, 2);
    s1 += __shfl_xor_sync(0xFFFFFFFFu, s1, 1);
    s1 += __shfl_xor_sync(0xFFFFFFFFu, s1, 2);
    const float x2a = s0, x2b = s1;

    // ---- MMA: 12 k-steps; ks 0-3 (hi,hi), 4-7 (lo,hi), 8-11 (hi,lo) ----
    const int g     = lane >> 3;
    const int nOffB = ((g & 2) ? 8 : 0) + (lane & 7);
    const int kB    = (g & 1) * 8;

    float acc[4][4];
    #pragma unroll
    for (int j = 0; j < 4; ++j)
        #pragma unroll
        for (int u = 0; u < 4; ++u) acc[j][u] = 0.f;

    #pragma unroll
    for (int ks = 0; ks < 12; ++ks) {
        const uint32_t* a = (ks < 4) ? &ahi[4 * ks]
                          : (ks < 8) ? &alo[4 * (ks - 4)]
                                     : &ahi[4 * (ks - 8)];
        const int kg = ((ks < 8) ? (ks & 3) * 16 : 128 + (ks & 3) * 16);
        #pragma unroll
        for (int nb = 0; nb < 2; ++nb) {
            const int nrow = wn * 32 + nb * 16 + nOffB;    // local proto row
            uint32_t b[4];
            ldsm_x4(b, smb + SM_B + sw((uint32_t)nrow * ROWB + (uint32_t)(kg + kB) * 2));
            mma_bf16(acc[2 * nb],     a, b[0], b[1]);
            mma_bf16(acc[2 * nb + 1], a, b[2], b[3]);
        }
    }

    // ---- epilogue straight from accumulators ----
    {
        const float Ba = 1.0f - x2a;
        const float Bb = 1.0f - x2b;
        float* orowa = out + (size_t)(n0 + r0) * KP + k0;
        float* orowb = orowa + 8 * KP;

        #pragma unroll
        for (int j = 0; j < 4; ++j) {
            const int c = wn * 32 + j * 8 + 2 * (lane & 3);  // local col
            const float2 p2 = *(const float2*)&p2_s[c];
            float2 oa, ob;
            oa.x = epi(acc[j][0], x2a, Ba, p2.x);
            oa.y = epi(acc[j][1], x2a, Ba, p2.y);
            ob.x = epi(acc[j][2], x2b, Bb, p2.x);
            ob.y = epi(acc[j][3], x2b, Bb, p2.y);
            *(float2*)(orowa + c) = oa;
            *(float2*)(orowb + c) = ob;
        }
    }
}

// ---------------------------------------------------------------------------
extern "C" void kernel_launch(void* const* d_in, const int* in_sizes, int n_in,
                              void* d_out, int out_size) {
    const float* x;
    const float* proto;
    int xs;
    if (in_sizes[0] == KP * D) {
        proto = (const float*)d_in[0];
        x     = (const float*)d_in[1];
        xs    = in_sizes[1];
    } else {
        x     = (const float*)d_in[0];
        proto = (const float*)d_in[1];
        xs    = in_sizes[0];
    }
    const int N = xs / D;  // 16384
    float* out = (float*)d_out;

    cudaFuncSetAttribute(geo_kernel, cudaFuncAttributeMaxDynamicSharedMemorySize, SM_DYN);
    dim3 grid(N / TM, KP / TK);
    geo_kernel<<<grid, NTH, SM_DYN>>>(x, proto, out);
}

// round 11
// speedup vs baseline: 1.2088x; 1.2088x over previous
#include <cuda_runtime.h>
#include <cuda_bf16.h>
#include <math.h>
#include <stdint.h>

#define D     64
#define TM    64        // x rows per CTA
#define KP    128       // all prototypes in every CTA
#define NTH   256
#define ROWB  384       // bytes per B row; chunk0=hi @0, chunk2=lo @+256

// smem layout
#define SM_B   0                      // 128 x 384B = 49152
#define SM_P2  49152                  // 128 floats
#define SM_DYN (SM_P2 + 512)          // 49664 B

static __device__ __forceinline__ uint32_t sw(uint32_t off) {
    return off ^ ((off >> 3) & 0x70);
}

static __device__ __forceinline__ uint32_t smem_u32(const void* p) {
    uint32_t a;
    asm("{ .reg .u64 t; cvta.to.shared.u64 t, %1; cvt.u32.u64 %0, t; }" : "=r"(a) : "l"(p));
    return a;
}

static __device__ __forceinline__ void ldsm_x4(uint32_t* r, uint32_t addr) {
    asm volatile("ldmatrix.sync.aligned.m8n8.x4.shared.b16 {%0,%1,%2,%3}, [%4];"
                 : "=r"(r[0]), "=r"(r[1]), "=r"(r[2]), "=r"(r[3]) : "r"(addr));
}

static __device__ __forceinline__ void mma_bf16(float* c, const uint32_t* a,
                                                uint32_t b0, uint32_t b1) {
    asm volatile(
        "mma.sync.aligned.m16n8k16.row.col.f32.bf16.bf16.f32 "
        "{%0,%1,%2,%3}, {%4,%5,%6,%7}, {%8,%9}, {%0,%1,%2,%3};"
        : "+f"(c[0]), "+f"(c[1]), "+f"(c[2]), "+f"(c[3])
        : "r"(a[0]), "r"(a[1]), "r"(a[2]), "r"(a[3]), "r"(b0), "r"(b1));
}

static __device__ __forceinline__ void split2(float v0, float v1,
                                              uint32_t& hi, uint32_t& lo) {
    __nv_bfloat162 h = __floats2bfloat162_rn(v0, v1);
    float r0 = v0 - __bfloat162float(__low2bfloat16(h));
    float r1 = v1 - __bfloat162float(__high2bfloat16(h));
    __nv_bfloat162 l = __floats2bfloat162_rn(r0, r1);
    hi = *reinterpret_cast<uint32_t*>(&h);
    lo = *reinterpret_cast<uint32_t*>(&l);
}

// num2 = A^2 x2 - 2AB xy + B^2 p2 == den^2 - den*(1-x2)(1-p2)  (verified R8/R9)
static __device__ __forceinline__ float epi(float xy, float x2, float Ba, float p2) {
    const float t   = fmaf(x2, p2, 1.0f);
    const float den = fmaxf(fmaf(-2.0f, xy, t), 1e-15f);
    const float bb  = fmaf(-Ba, p2, Ba);              // Ba*(1-p2)
    float G = fmaf(den, den, -(den * bb));            // = |num|^2
    G = fmaxf(G, 1e-30f);
    float s = G * rsqrtf(G);                          // sqrt(G)
    s = fminf(s, 0.99999f * den);                     // z <= 1 - 1e-5
    const float dist = (__log2f(den + s) - __log2f(den - s)) * 0.6931471805599453f;
    return -dist * dist;
}

// ---------------------------------------------------------------------------
// grid = N/64 = 256 CTAs, 256 threads. Single __syncthreads.
//  B-prep: one proto read per element; norm via 1 shfl; regs reused for
//          split-bf16; 8 STS.128 per thread, swizzle applied per 16B store.
//  A: direct global->reg fragments + in-reg split + shfl x^2.
//  MMA: B chunk0 frags loaded once, feed both ahi and alo k-steps.
// ---------------------------------------------------------------------------
__global__ void __launch_bounds__(NTH)
geo_kernel(const float* __restrict__ x, const float* __restrict__ proto,
           float* __restrict__ out) {
    extern __shared__ char sm[];
    const uint32_t smb = smem_u32(sm);
    float* p2_s = (float*)(sm + SM_P2);

    const int tid  = threadIdx.x;
    const int wid  = tid >> 5;
    const int lane = tid & 31;
    const int n0   = blockIdx.x * TM;

    // ---- A: load fragments + immediate split + x^2 (no smem, no barrier) ----
    const int wm = wid & 3;
    const int wn = wid >> 2;
    const int r0 = wm * 16 + (lane >> 2);
    const float* xr0 = x + (size_t)(n0 + r0) * D + 2 * (lane & 3);
    const float* xr1 = xr0 + 8 * D;

    uint32_t ahi[16], alo[16];
    float s0 = 0.f, s1 = 0.f;
    #pragma unroll
    for (int t = 0; t < 4; ++t) {
        float2 v00 = *(const float2*)(xr0 + t * 16);        // (r0,   k=16t+c)
        float2 v10 = *(const float2*)(xr1 + t * 16);        // (r0+8, k)
        float2 v01 = *(const float2*)(xr0 + t * 16 + 8);    // (r0,   k+8)
        float2 v11 = *(const float2*)(xr1 + t * 16 + 8);    // (r0+8, k+8)
        s0 += v00.x * v00.x + v00.y * v00.y + v01.x * v01.x + v01.y * v01.y;
        s1 += v10.x * v10.x + v10.y * v10.y + v11.x * v11.x + v11.y * v11.y;
        split2(v00.x, v00.y, ahi[4 * t + 0], alo[4 * t + 0]);
        split2(v10.x, v10.y, ahi[4 * t + 1], alo[4 * t + 1]);
        split2(v01.x, v01.y, ahi[4 * t + 2], alo[4 * t + 2]);
        split2(v11.x, v11.y, ahi[4 * t + 3], alo[4 * t + 3]);
    }
    s0 += __shfl_xor_sync(0xFFFFFFFFu, s0, 1);
    s0 += __shfl_xor_sync(0xFFFFFFFFu, s0, 2);
    s1 += __shfl_xor_sync(0xFFFFFFFFu, s1, 1);
    s1 += __shfl_xor_sync(0xFFFFFFFFu, s1, 2);
    const float x2a = s0, x2b = s1;

    // ---- B-prep: row r = tid>>1, k-half h = tid&1 (32 elems, one read) ----
    {
        const int r = tid >> 1;
        const int h = tid & 1;
        const float4* p4 = (const float4*)(proto) + (size_t)r * 16 + h * 8;
        float4 v[8];
        float s = 0.f;
        #pragma unroll
        for (int i = 0; i < 8; ++i) {
            v[i] = p4[i];
            s += v[i].x * v[i].x + v[i].y * v[i].y + v[i].z * v[i].z + v[i].w * v[i].w;
        }
        s += __shfl_xor_sync(0xFFFFFFFFu, s, 1);     // full row norm^2
        const float n  = fmaxf(sqrtf(s), 1e-15f);
        const float sc = fminf(1.0f, 0.999f / n);    // (1-BALL_EPS)/sqrt(c)
        if (h == 0) p2_s[r] = s * sc * sc;

        // split 32 elems -> 16 hi + 16 lo uint32
        uint32_t hi[16], lo[16];
        #pragma unroll
        for (int i = 0; i < 8; ++i) {
            split2(v[i].x * sc, v[i].y * sc, hi[2 * i],     lo[2 * i]);
            split2(v[i].z * sc, v[i].w * sc, hi[2 * i + 1], lo[2 * i + 1]);
        }
        // Swizzle applied PER 16B STORE (exact at 16B granularity; the XOR
        // mask touches bits [6:4], so it is NOT translation-invariant across
        // a 64B chunk -- the R10 bug).
        const uint32_t rbase = (uint32_t)r * ROWB + (uint32_t)h * 64;
        #pragma unroll
        for (int j = 0; j < 4; ++j) {
            *(uint4*)(sm + SM_B + sw(rbase + j * 16)) =
                make_uint4(hi[4 * j], hi[4 * j + 1], hi[4 * j + 2], hi[4 * j + 3]);
            *(uint4*)(sm + SM_B + sw(rbase + 256 + j * 16)) =
                make_uint4(lo[4 * j], lo[4 * j + 1], lo[4 * j + 2], lo[4 * j + 3]);
        }
    }
    __syncthreads();

    // ---- MMA: chunk0 B frags reused for (ahi,Bhi) and (alo,Bhi) ----
    const int g     = lane >> 3;
    const int nOffB = ((g & 2) ? 8 : 0) + (lane & 7);
    const int kB    = (g & 1) * 8;

    float acc[8][4];
    #pragma unroll
    for (int j = 0; j < 8; ++j)
        #pragma unroll
        for (int u = 0; u < 4; ++u) acc[j][u] = 0.f;

    #pragma unroll
    for (int kgi = 0; kgi < 4; ++kgi) {               // chunk0: hi B
        const int kg = kgi * 16;
        #pragma unroll
        for (int nb = 0; nb < 4; ++nb) {
            const int nrow = wn * 64 + nb * 16 + nOffB;
            uint32_t b[4];
            ldsm_x4(b, smb + SM_B + sw((uint32_t)nrow * ROWB + (uint32_t)(kg + kB) * 2));
            mma_bf16(acc[2 * nb],     &ahi[4 * kgi], b[0], b[1]);
            mma_bf16(acc[2 * nb + 1], &ahi[4 * kgi], b[2], b[3]);
            mma_bf16(acc[2 * nb],     &alo[4 * kgi], b[0], b[1]);
            mma_bf16(acc[2 * nb + 1], &alo[4 * kgi], b[2], b[3]);
        }
    }
    #pragma unroll
    for (int kgi = 0; kgi < 4; ++kgi) {               // chunk2: lo B, hi A
        const int kg = 128 + kgi * 16;
        #pragma unroll
        for (int nb = 0; nb < 4; ++nb) {
            const int nrow = wn * 64 + nb * 16 + nOffB;
            uint32_t b[4];
            ldsm_x4(b, smb + SM_B + sw((uint32_t)nrow * ROWB + (uint32_t)(kg + kB) * 2));
            mma_bf16(acc[2 * nb],     &ahi[4 * kgi], b[0], b[1]);
            mma_bf16(acc[2 * nb + 1], &ahi[4 * kgi], b[2], b[3]);
        }
    }

    // ---- epilogue straight from accumulators ----
    {
        const float Ba = 1.0f - x2a;
        const float Bb = 1.0f - x2b;
        float* orowa = out + (size_t)(n0 + r0) * KP;
        float* orowb = orowa + 8 * KP;

        #pragma unroll
        for (int j = 0; j < 8; ++j) {
            const int c = wn * 64 + j * 8 + 2 * (lane & 3);
            const float2 p2 = *(const float2*)&p2_s[c];
            float2 oa, ob;
            oa.x = epi(acc[j][0], x2a, Ba, p2.x);
            oa.y = epi(acc[j][1], x2a, Ba, p2.y);
            ob.x = epi(acc[j][2], x2b, Bb, p2.x);
            ob.y = epi(acc[j][3], x2b, Bb, p2.y);
            *(float2*)(orowa + c) = oa;
            *(float2*)(orowb + c) = ob;
        }
    }
}

// ---------------------------------------------------------------------------
extern "C" void kernel_launch(void* const* d_in, const int* in_sizes, int n_in,
                              void* d_out, int out_size) {
    const float* x;
    const float* proto;
    int xs;
    if (in_sizes[0] == KP * D) {
        proto = (const float*)d_in[0];
        x     = (const float*)d_in[1];
        xs    = in_sizes[1];
    } else {
        x     = (const float*)d_in[0];
        proto = (const float*)d_in[1];
        xs    = in_sizes[0];
    }
    const int N = xs / D;  // 16384
    float* out = (float*)d_out;

    cudaFuncSetAttribute(geo_kernel, cudaFuncAttributeMaxDynamicSharedMemorySize, SM_DYN);
    geo_kernel<<<N / TM, NTH, SM_DYN>>>(x, proto, out);
}